// round 1
// baseline (speedup 1.0000x reference)
#include <cuda_runtime.h>

typedef unsigned long long ull;

#define N_ATOMS   262144
#define TILE      32
#define NTILES    (N_ATOMS / TILE)   /* 8192 */
#define THREADS   256
#define GRID      148

/* ---------------- smem layout (float offsets) ---------------- */
#define OFF_WV1   0                  /* 128x128 = 16384 */
#define OFF_W1A   16384              /* 192x64  = 12288 */
#define OFF_W1B   28672              /* 64x128  = 8192  */
#define OFF_U     36864              /* union region, 12640 floats */
#define OFF_VW    49504              /* 96 x 65 = 6240  */
#define OFF_S     55744              /* small region, 640 */
#define SMEM_FLOATS 56384
#define SMEM_BYTES  (SMEM_FLOATS * 4)   /* 225536 B < 232448 B limit */

/* union sub-offsets (relative to OFF_U) */
#define U_L1T   0        /* l1 transposed: 128 rows x pitch 97 = 12416 */
#define U_CTXT  0        /* ctx transposed: 192 rows x pitch 33 = 6336 */
#define U_HT    6336     /* h transposed: 64 x 33 = 2112 */
#define U_ST    8448     /* s_out transposed: 64 x 33 = 2112 */
#define U_GATE  10560    /* gate: 32 x 65 = 2080 */

/* small region (relative to OFF_S) */
#define S_B1A 0
#define S_B1B 64
#define S_WV2 192
#define S_W2A 320
#define S_SC  388     /* [0]=b2a, [1]=W2b[0][1], [2]=b2b[1] */
#define S_M0  392     /* vmix2 col0, 96 */
#define S_M1  488     /* vmix2 col1, 96 */
#define S_G2  584     /* 1000*gate2, 32 */

__device__ __forceinline__ ull pack2(float x, float y) {
    ull r; asm("mov.b64 %0, {%1, %2};" : "=l"(r) : "f"(x), "f"(y)); return r;
}
__device__ __forceinline__ void unpack2(ull v, float& x, float& y) {
    asm("mov.b64 {%0, %1}, %2;" : "=f"(x), "=f"(y) : "l"(v));
}
__device__ __forceinline__ ull fma2(ull a, ull b, ull c) {
    ull d; asm("fma.rn.f32x2 %0, %1, %2, %3;" : "=l"(d) : "l"(a), "l"(b), "l"(c)); return d;
}
__device__ __forceinline__ float silu(float x) {
    return x * (1.0f / (1.0f + __expf(-x)));
}

__global__ void __launch_bounds__(THREADS, 1)
hessdiag_fused(const float* __restrict__ l0, const float* __restrict__ l1,
               const float* __restrict__ Wv1, const float* __restrict__ W1a,
               const float* __restrict__ b1a, const float* __restrict__ W1b,
               const float* __restrict__ b1b, const float* __restrict__ Wv2,
               const float* __restrict__ W2a, const float* __restrict__ b2a,
               const float* __restrict__ W2b, const float* __restrict__ b2b,
               float* __restrict__ out)
{
    extern __shared__ float sm[];
    const int t = threadIdx.x;

    /* ---- load all weights into smem once ---- */
    for (int i = t; i < 16384; i += THREADS) sm[OFF_WV1 + i] = Wv1[i];
    for (int i = t; i < 12288; i += THREADS) sm[OFF_W1A + i] = W1a[i];
    for (int i = t; i < 8192;  i += THREADS) sm[OFF_W1B + i] = W1b[i];
    if (t < 64)  sm[OFF_S + S_B1A + t] = b1a[t];
    if (t < 128) sm[OFF_S + S_B1B + t] = b1b[t];
    if (t < 128) sm[OFF_S + S_WV2 + t] = Wv2[t];
    if (t < 65)  sm[OFF_S + S_W2A + t] = W2a[t];
    if (t == 0) {
        sm[OFF_S + S_SC + 0] = b2a[0];
        sm[OFF_S + S_SC + 1] = W2b[1];   /* W2b shape (1,2): col 1 */
        sm[OFF_S + S_SC + 2] = b2b[1];
    }

    const int tx = t & 15;      /* phase-1 col group */
    const int ty = t >> 4;      /* phase-1 row group */
    const int r0 = ty * 6;      /* 6 rows (2 atoms x 3) */
    const int atom8 = t >> 3;   /* phase-2/3 atom (0..31) */
    const int fg = t & 7;       /* phase-2/3 col group */

    for (int tile = blockIdx.x; tile < NTILES; tile += gridDim.x) {
        const int base = tile * TILE;

        /* ---- P0: l1 -> transposed L1T[k][r], pitch 97 (coalesced gmem) ---- */
        {
            const float* g = l1 + (size_t)base * 384;
            #pragma unroll
            for (int e = 0; e < 48; e++) {
                int gi = e * THREADS + t;
                int i  = gi / 384;
                int rem = gi - i * 384;
                int a  = rem >> 7;
                int k  = rem & 127;
                sm[OFF_U + U_L1T + k * 97 + i * 3 + a] = g[gi];
            }
        }
        __syncthreads();

        /* ---- P1: vmix = l1_tile @ Wv1 (96 x 128), f32x2 packed FMA ----
           thread owns rows r0..r0+5, cols {4tx..4tx+3} (vV) and {64+4tx..+3} (vW) */
        ull accV[6][2], accW[6][2];
        {
            const ull z = pack2(0.f, 0.f);
            #pragma unroll
            for (int j = 0; j < 6; j++) {
                accV[j][0] = z; accV[j][1] = z; accW[j][0] = z; accW[j][1] = z;
            }
            const float* L  = &sm[OFF_U + U_L1T + r0];
            const float* WV = &sm[OFF_WV1 + 4 * tx];
            #pragma unroll 2
            for (int k = 0; k < 128; k++) {
                float4 bv = *reinterpret_cast<const float4*>(WV + k * 128);
                float4 bw = *reinterpret_cast<const float4*>(WV + k * 128 + 64);
                ull bv0 = pack2(bv.x, bv.y), bv1 = pack2(bv.z, bv.w);
                ull bw0 = pack2(bw.x, bw.y), bw1 = pack2(bw.z, bw.w);
                #pragma unroll
                for (int j = 0; j < 6; j++) {
                    float av = L[k * 97 + j];
                    ull a2 = pack2(av, av);
                    accV[j][0] = fma2(a2, bv0, accV[j][0]);
                    accV[j][1] = fma2(a2, bv1, accV[j][1]);
                    accW[j][0] = fma2(a2, bw0, accW[j][0]);
                    accW[j][1] = fma2(a2, bw1, accW[j][1]);
                }
            }
        }
        /* store vW tile (region disjoint from L1T -> no barrier needed yet) */
        #pragma unroll
        for (int j = 0; j < 6; j++) {
            float w0, w1, w2, w3;
            unpack2(accW[j][0], w0, w1);
            unpack2(accW[j][1], w2, w3);
            float* p = &sm[OFF_VW + (r0 + j) * 65 + 4 * tx];
            p[0] = w0; p[1] = w1; p[2] = w2; p[3] = w3;
        }
        /* norms over a-axis, kept in registers until L1T retires */
        float vn2[2][4];
        #pragma unroll
        for (int i = 0; i < 2; i++) {
            vn2[i][0] = vn2[i][1] = vn2[i][2] = vn2[i][3] = 0.f;
            #pragma unroll
            for (int a = 0; a < 3; a++) {
                float x0, x1, x2, x3;
                unpack2(accV[3 * i + a][0], x0, x1);
                unpack2(accV[3 * i + a][1], x2, x3);
                vn2[i][0] += x0 * x0; vn2[i][1] += x1 * x1;
                vn2[i][2] += x2 * x2; vn2[i][3] += x3 * x3;
            }
        }
        __syncthreads();   /* all reads of L1T complete */

        /* ---- build ctx^T: rows 0..127 = l0, rows 128..191 = |vV| ---- */
        {
            const float* g = l0 + (size_t)base * 128;
            #pragma unroll
            for (int e = 0; e < 16; e++) {
                int gi = e * THREADS + t;
                int i  = gi >> 7;
                int k  = gi & 127;
                sm[OFF_U + U_CTXT + k * 33 + i] = g[gi];
            }
        }
        #pragma unroll
        for (int i = 0; i < 2; i++) {
            #pragma unroll
            for (int c = 0; c < 4; c++)
                sm[OFF_U + U_CTXT + (128 + 4 * tx + c) * 33 + (2 * ty + i)] = sqrtf(vn2[i][c]);
        }
        __syncthreads();

        /* ---- P2: h = silu(ctx @ W1a + b1a), (32 x 64) ---- */
        {
            float acc2[8];
            #pragma unroll
            for (int j = 0; j < 2; j++)
                #pragma unroll
                for (int c = 0; c < 4; c++)
                    acc2[4 * j + c] = sm[OFF_S + S_B1A + 4 * fg + 32 * j + c];
            const float* C = &sm[OFF_U + U_CTXT + atom8];
            const float* W = &sm[OFF_W1A + 4 * fg];
            #pragma unroll 2
            for (int k = 0; k < 192; k++) {
                float a = C[k * 33];
                float4 w0 = *reinterpret_cast<const float4*>(W + k * 64);
                float4 w1 = *reinterpret_cast<const float4*>(W + k * 64 + 32);
                acc2[0] += a * w0.x; acc2[1] += a * w0.y;
                acc2[2] += a * w0.z; acc2[3] += a * w0.w;
                acc2[4] += a * w1.x; acc2[5] += a * w1.y;
                acc2[6] += a * w1.z; acc2[7] += a * w1.w;
            }
            #pragma unroll
            for (int j = 0; j < 2; j++)
                #pragma unroll
                for (int c = 0; c < 4; c++) {
                    int f = 4 * fg + 32 * j + c;
                    sm[OFF_U + U_HT + f * 33 + atom8] = silu(acc2[4 * j + c]);
                }
        }
        __syncthreads();

        /* ---- P3: y = h @ W1b + b1b (32 x 128): s half -> silu -> ST, gate half -> GATE ---- */
        {
            float acc3[16];
            #pragma unroll
            for (int j = 0; j < 4; j++)
                #pragma unroll
                for (int c = 0; c < 4; c++)
                    acc3[4 * j + c] = sm[OFF_S + S_B1B + 4 * fg + 32 * j + c];
            const float* H = &sm[OFF_U + U_HT + atom8];
            const float* W = &sm[OFF_W1B + 4 * fg];
            #pragma unroll 2
            for (int k = 0; k < 64; k++) {
                float a = H[k * 33];
                #pragma unroll
                for (int j = 0; j < 4; j++) {
                    float4 w = *reinterpret_cast<const float4*>(W + k * 128 + 32 * j);
                    acc3[4 * j + 0] += a * w.x; acc3[4 * j + 1] += a * w.y;
                    acc3[4 * j + 2] += a * w.z; acc3[4 * j + 3] += a * w.w;
                }
            }
            #pragma unroll
            for (int j = 0; j < 4; j++)
                #pragma unroll
                for (int c = 0; c < 4; c++) {
                    int f = 4 * fg + 32 * j + c;
                    float y = acc3[4 * j + c];
                    if (f < 64) sm[OFF_U + U_ST + f * 33 + atom8] = silu(y);
                    else        sm[OFF_U + U_GATE + atom8 * 65 + (f - 64)] = y;
                }
        }
        __syncthreads();

        /* ---- P4: vmix2[r][0..1] = sum_f gate[n][f]*vW[r][f]*Wv2[f][:] ---- */
        if (t < 96) {
            int n = t / 3;
            const float* G  = &sm[OFF_U + U_GATE + n * 65];
            const float* V  = &sm[OFF_VW + t * 65];
            const float* S2 = &sm[OFF_S + S_WV2];
            float m0 = 0.f, m1 = 0.f;
            #pragma unroll 4
            for (int f = 0; f < 64; f++) {
                float p = G[f] * V[f];
                m0 += p * S2[2 * f];
                m1 += p * S2[2 * f + 1];
            }
            sm[OFF_S + S_M0 + t] = m0;
            sm[OFF_S + S_M1 + t] = m1;
        }
        __syncthreads();

        /* ---- P5: scalar head per atom ---- */
        if (t < 32) {
            float q0 = sm[OFF_S + S_M0 + 3 * t + 0];
            float q1 = sm[OFF_S + S_M0 + 3 * t + 1];
            float q2 = sm[OFF_S + S_M0 + 3 * t + 2];
            float d = sm[OFF_S + S_SC + 0] +
                      sqrtf(q0 * q0 + q1 * q1 + q2 * q2) * sm[OFF_S + S_W2A + 64];
            const float* S = &sm[OFF_U + U_ST + t];
            #pragma unroll 4
            for (int k = 0; k < 64; k++) d += S[k * 33] * sm[OFF_S + S_W2A + k];
            float h2 = silu(d);
            sm[OFF_S + S_G2 + t] = 1000.f * (h2 * sm[OFF_S + S_SC + 1] + sm[OFF_S + S_SC + 2]);
        }
        __syncthreads();

        /* ---- P6: out[n*3+a] = 1000*gate2[n]*vmix2[r][1] (coalesced) ---- */
        if (t < 96) {
            out[(size_t)tile * 96 + t] = sm[OFF_S + S_G2 + t / 3] * sm[OFF_S + S_M1 + t];
        }
        /* next P0 writes the union region; its readers all finished before the
           P5-end barrier, and P6 touches only the small region -> safe. */
    }
}

extern "C" void kernel_launch(void* const* d_in, const int* in_sizes, int n_in,
                              void* d_out, int out_size) {
    const float* l0  = (const float*)d_in[0];
    const float* l1  = (const float*)d_in[1];
    /* d_in[2] = idx_m (int64) — unused by the reference computation */
    const float* Wv1 = (const float*)d_in[3];
    const float* W1a = (const float*)d_in[4];
    const float* b1a = (const float*)d_in[5];
    const float* W1b = (const float*)d_in[6];
    const float* b1b = (const float*)d_in[7];
    const float* Wv2 = (const float*)d_in[8];
    const float* W2a = (const float*)d_in[9];
    const float* b2a = (const float*)d_in[10];
    const float* W2b = (const float*)d_in[11];
    const float* b2b = (const float*)d_in[12];

    cudaFuncSetAttribute(hessdiag_fused,
                         cudaFuncAttributeMaxDynamicSharedMemorySize, SMEM_BYTES);
    hessdiag_fused<<<GRID, THREADS, SMEM_BYTES>>>(
        l0, l1, Wv1, W1a, b1a, W1b, b1b, Wv2, W2a, b2a, W2b, b2b, (float*)d_out);
}